// round 6
// baseline (speedup 1.0000x reference)
#include <cuda_runtime.h>
#include <math.h>

#define B 32
#define C 256
#define HW 56
#define BC (B*C)
#define POOL 7
#define NN 64
#define HEADS 8
#define HD 32
#define EPS 1e-5f

// ---------------- scratch ----------------
__device__ float g_mean_h[BC * HW];
__device__ float g_mean_w[BC * HW];
__device__ float g_attn_h[BC * HW];
__device__ float g_attn_w[BC * HW];
__device__ float g_pooled[BC * NN];
__device__ float g_bsum[B];
__device__ float g_bsumsq[B];
__device__ float g_ca[BC];
__device__ int   g_cnt_sa[B * 4];   // per (batch, group); reset by epilogue
__device__ int   g_cnt_pool[B];     // per batch; reset by epilogue

// ============ kernel 1: means + fused sa_branch epilogue ===================
__global__ __launch_bounds__(256) void k_means_sa(
    const float* __restrict__ x,
    const float* __restrict__ w3, const float* __restrict__ b3,
    const float* __restrict__ w5, const float* __restrict__ b5,
    const float* __restrict__ w7, const float* __restrict__ b7,
    const float* __restrict__ w9, const float* __restrict__ b9,
    const float* __restrict__ sh, const float* __restrict__ bh,
    const float* __restrict__ sw, const float* __restrict__ bw)
{
    __shared__ __align__(16) float buf[3584];   // sp needs 3192; sa stage needs 3584
    __shared__ float r1[8], r2[8], sstat[2];
    __shared__ int sflag;
    float (*sp)[HW + 1] = (float(*)[HW + 1])buf;

    int bc = blockIdx.x, tid = threadIdx.x;
    if (tid == 0 && bc < B) { g_bsum[bc] = 0.f; g_bsumsq[bc] = 0.f; }
    const float4* xp = (const float4*)(x + (size_t)bc * HW * HW);
    #pragma unroll
    for (int k = 0; k < 4; ++k) {
        int f = tid + 256 * k;
        if (f < 784) {
            float4 v = xp[f];
            int r = f / 14, c = (f - r * 14) * 4;
            sp[r][c]     = v.x;
            sp[r][c + 1] = v.y;
            sp[r][c + 2] = v.z;
            sp[r][c + 3] = v.w;
        }
    }
    __syncthreads();
    if (tid < HW) {
        float rs = 0.f, cs = 0.f;
        #pragma unroll
        for (int w = 0; w < HW; ++w) { rs += sp[tid][w]; cs += sp[w][tid]; }
        g_mean_h[bc * HW + tid] = rs * (1.f / 56.f);
        g_mean_w[bc * HW + tid] = cs * (1.f / 56.f);
    }

    // -------- last-block-of-(b,g) epilogue: run sa_branch for both axes ----
    int g = (bc >> 6) & 3, b = bc >> 8;
    int cidx = b * 4 + g;
    __threadfence();
    __syncthreads();
    if (tid == 0) sflag = (atomicAdd(&g_cnt_sa[cidx], 1) == 63);
    __syncthreads();
    if (!sflag) return;

    const float* wf; const float* bf; int ksz;
    if (g == 0)      { wf = w3; bf = b3; ksz = 3; }
    else if (g == 1) { wf = w5; bf = b5; ksz = 5; }
    else if (g == 2) { wf = w7; bf = b7; ksz = 7; }
    else             { wf = w9; bf = b9; ksz = 9; }
    int pad = ksz >> 1;
    size_t base = ((size_t)b * C + g * 64) * HW;
    int lane = tid & 31, wid = tid >> 5;

    for (int br = 0; br < 2; ++br) {
        const float* in  = (br == 0) ? g_mean_h : g_mean_w;
        float*       out = (br == 0) ? g_attn_h : g_attn_w;
        const float* sc  = (br == 0) ? sh : sw;
        const float* bi  = (br == 0) ? bh : bw;
        const float4* in4  = (const float4*)(in + base);
        float4*       out4 = (float4*)(out + base);
        __syncthreads();
        #pragma unroll
        for (int k = 0; k < 4; ++k) {
            int f = tid + 256 * k;
            if (f < 896) ((float4*)buf)[f] = in4[f];
        }
        __syncthreads();

        float o[16];
        int   cch[4];
        float s = 0.f, ss = 0.f;
        #pragma unroll
        for (int k = 0; k < 4; ++k) {
            int f = tid + 256 * k;
            if (f < 896) {
                int c  = f / 14;
                int l0 = (f - c * 14) * 4;
                cch[k] = c;
                const float* row = buf + c * HW;
                #pragma unroll
                for (int q = 0; q < 4; ++q) {
                    int l = l0 + q;
                    float acc = bf[c];
                    for (int j = 0; j < ksz; ++j) {
                        int idx = l + j - pad;
                        if (idx >= 0 && idx < HW) acc = fmaf(wf[c * ksz + j], row[idx], acc);
                    }
                    o[k * 4 + q] = acc;
                    s += acc; ss = fmaf(acc, acc, ss);
                }
            } else cch[k] = -1;
        }
        #pragma unroll
        for (int off = 16; off; off >>= 1) {
            s  += __shfl_xor_sync(~0u, s, off);
            ss += __shfl_xor_sync(~0u, ss, off);
        }
        if (lane == 0) { r1[wid] = s; r2[wid] = ss; }
        __syncthreads();
        if (tid == 0) {
            float a = 0.f, b2 = 0.f;
            #pragma unroll
            for (int w = 0; w < 8; ++w) { a += r1[w]; b2 += r2[w]; }
            float mean = a * (1.f / 3584.f);
            float var  = b2 * (1.f / 3584.f) - mean * mean;
            sstat[0] = mean;
            sstat[1] = rsqrtf(var + EPS);
        }
        __syncthreads();
        float mean = sstat[0], rstd = sstat[1];
        #pragma unroll
        for (int k = 0; k < 4; ++k) {
            if (cch[k] >= 0) {
                int f = tid + 256 * k;
                int cg = g * 64 + cch[k];
                float a_ = rstd * sc[cg], b_ = bi[cg] - mean * a_;
                float4 v;
                v.x = 1.f / (1.f + __expf(-(o[k*4+0] * a_ + b_)));
                v.y = 1.f / (1.f + __expf(-(o[k*4+1] * a_ + b_)));
                v.z = 1.f / (1.f + __expf(-(o[k*4+2] * a_ + b_)));
                v.w = 1.f / (1.f + __expf(-(o[k*4+3] * a_ + b_)));
                out4[f] = v;
            }
        }
        __syncthreads();
    }
    if (tid == 0) g_cnt_sa[cidx] = 0;   // reset for graph replay
}

// ============ kernel 2: pool + fused attention epilogue ====================
// smem plane stride 60 floats (15 float4): STS.128 staging, mild LDS conflicts
__global__ __launch_bounds__(256) void k_pool_attn(
    const float* __restrict__ x,
    const float* __restrict__ ns, const float* __restrict__ nb,
    const float* __restrict__ qw, const float* __restrict__ kw,
    const float* __restrict__ vw)
{
    __shared__ __align__(16) float buf[3360];   // sp[56][60]; reused as xs[32*68]
    __shared__ __align__(16) float sah[HW], saw[HW];
    __shared__ float rs_[8], rss_[8], svbar[HD];
    __shared__ int sflag;

    int bc = blockIdx.x, tid = threadIdx.x;
    int b = bc >> 8;
    if (tid < HW) { sah[tid] = g_attn_h[bc * HW + tid]; saw[tid] = g_attn_w[bc * HW + tid]; }
    __syncthreads();
    const float4* xp = (const float4*)(x + (size_t)bc * HW * HW);
    #pragma unroll
    for (int k = 0; k < 4; ++k) {
        int f = tid + 256 * k;
        if (f < 784) {
            float4 v = xp[f];
            int r = f / 14, c4 = f - r * 14;
            float a = sah[r];
            float4 w4 = ((const float4*)saw)[c4];
            float4 t;
            t.x = v.x * a * w4.x;
            t.y = v.y * a * w4.y;
            t.z = v.z * a * w4.z;
            t.w = v.w * a * w4.w;
            ((float4*)buf)[r * 15 + c4] = t;      // STS.128, stride 60 floats
        }
    }
    __syncthreads();
    // pooling: 4 threads per cell; sub handles rows {sub, sub+4}
    int cell = tid >> 2, sub = tid & 3;
    int pi = cell >> 3, pj = cell & 7;
    const float* rowA = buf + (POOL * pi + sub) * 60 + POOL * pj;
    float sum = 0.f;
    #pragma unroll
    for (int v = 0; v < POOL; ++v) sum += rowA[v];
    if (sub < 3) {
        const float* rowB = rowA + 4 * 60;
        #pragma unroll
        for (int v = 0; v < POOL; ++v) sum += rowB[v];
    }
    sum += __shfl_xor_sync(~0u, sum, 1);
    sum += __shfl_xor_sync(~0u, sum, 2);
    float pv = 0.f;
    if (sub == 0) {
        pv = sum * (1.f / 49.f);
        g_pooled[bc * NN + cell] = pv;
    }
    float s = pv, ss = pv * pv;
    #pragma unroll
    for (int o = 16; o; o >>= 1) { s += __shfl_xor_sync(~0u, s, o); ss += __shfl_xor_sync(~0u, ss, o); }
    int lane = tid & 31, wid = tid >> 5;
    if (lane == 0) { rs_[wid] = s; rss_[wid] = ss; }
    __syncthreads();
    if (tid == 0) {
        float a = 0.f, c2 = 0.f;
        #pragma unroll
        for (int w = 0; w < 8; ++w) { a += rs_[w]; c2 += rss_[w]; }
        atomicAdd(&g_bsum[b], a);
        atomicAdd(&g_bsumsq[b], c2);
    }

    // -------- last-block-of-batch epilogue: attention for all 8 heads ------
    __threadfence();
    __syncthreads();
    if (tid == 0) sflag = (atomicAdd(&g_cnt_pool[b], 1) == 255);
    __syncthreads();
    if (!sflag) return;
    __threadfence();   // acquire: other blocks' g_pooled / g_bsum writes

    float bs = g_bsum[b], bss = g_bsumsq[b];
    float mu = bs * (1.f / 16384.f);
    float var = bss * (1.f / 16384.f) - mu * mu;
    float rstd = rsqrtf(var + EPS);
    const float scale = 0.17677669529663687f;   // 32^-0.5
    int wi = tid >> 5;

    for (int h = 0; h < HEADS; ++h) {
        __syncthreads();
        const float4* p4 = (const float4*)(g_pooled + ((size_t)b * C + h * HD) * NN);
        #pragma unroll
        for (int k = 0; k < 2; ++k) {
            int f = tid + 256 * k;
            float4 v = p4[f];
            int e = f >> 4;
            int c = h * HD + e;
            float a_ = rstd * ns[c], b_ = nb[c] - mu * a_;
            v.x = v.x * a_ + b_;
            v.y = v.y * a_ + b_;
            v.z = v.z * a_ + b_;
            v.w = v.w * a_ + b_;
            ((float4*)buf)[e * 17 + (f & 15)] = v;   // xs stride 68 floats
        }
        __syncthreads();
        {
            float sv[4];
            #pragma unroll
            for (int dd = 0; dd < 4; ++dd) {
                int row = wi * 4 + dd;
                sv[dd] = buf[row * 68 + lane] + buf[row * 68 + lane + 32];
            }
            #pragma unroll
            for (int o = 16; o; o >>= 1)
                #pragma unroll
                for (int dd = 0; dd < 4; ++dd)
                    sv[dd] += __shfl_xor_sync(~0u, sv[dd], o);
            if (lane == 0) {
                #pragma unroll
                for (int dd = 0; dd < 4; ++dd) {
                    int row = wi * 4 + dd;
                    svbar[row] = sv[dd] * (1.f / 64.f) * vw[h * HD + row];
                }
            }
        }
        __syncthreads();

        float kwe = kw[h * HD + lane];
        float vb  = svbar[lane];
        int d0 = wi * 4;
        const float4* xs4 = (const float4*)buf;
        float acc[4];
        #pragma unroll
        for (int dd = 0; dd < 4; ++dd) acc[dd] = 0.f;
        #pragma unroll
        for (int j = 0; j < 16; ++j) {
            float4 t = xs4[lane * 17 + j];
            #pragma unroll
            for (int dd = 0; dd < 4; ++dd) {
                float4 q = xs4[(d0 + dd) * 17 + j];
                acc[dd] = fmaf(t.x, q.x, acc[dd]);
                acc[dd] = fmaf(t.y, q.y, acc[dd]);
                acc[dd] = fmaf(t.z, q.z, acc[dd]);
                acc[dd] = fmaf(t.w, q.w, acc[dd]);
            }
        }
        float sarr[4], m[4], pe[4], Z[4], num[4];
        #pragma unroll
        for (int dd = 0; dd < 4; ++dd) {
            sarr[dd] = acc[dd] * qw[h * HD + d0 + dd] * kwe * scale;
            m[dd] = sarr[dd];
        }
        #pragma unroll
        for (int o = 16; o; o >>= 1)
            #pragma unroll
            for (int dd = 0; dd < 4; ++dd)
                m[dd] = fmaxf(m[dd], __shfl_xor_sync(~0u, m[dd], o));
        #pragma unroll
        for (int dd = 0; dd < 4; ++dd) {
            pe[dd]  = __expf(sarr[dd] - m[dd]);
            Z[dd]   = pe[dd];
            num[dd] = pe[dd] * vb;
        }
        #pragma unroll
        for (int o = 16; o; o >>= 1)
            #pragma unroll
            for (int dd = 0; dd < 4; ++dd) {
                Z[dd]   += __shfl_xor_sync(~0u, Z[dd], o);
                num[dd] += __shfl_xor_sync(~0u, num[dd], o);
            }
        if (lane == 0) {
            #pragma unroll
            for (int dd = 0; dd < 4; ++dd)
                g_ca[b * C + h * HD + d0 + dd] = 1.f / (1.f + __expf(-(num[dd] / Z[dd])));
        }
    }
    if (tid == 0) g_cnt_pool[b] = 0;   // reset for graph replay
}

// ============ kernel 3: out = ca * x * ah * aw =============================
__global__ __launch_bounds__(256) void k_final(const float* __restrict__ x,
                                               float* __restrict__ out) {
    __shared__ float sca[HW];
    __shared__ __align__(16) float saw[HW];
    int bc = blockIdx.x, tid = threadIdx.x;
    float ca = g_ca[bc];
    if (tid < HW)                     sca[tid] = ca * g_attn_h[bc * HW + tid];
    else if (tid >= 64 && tid < 120)  saw[tid - 64] = g_attn_w[bc * HW + tid - 64];
    __syncthreads();
    const float4* xp = (const float4*)(x + (size_t)bc * HW * HW);
    float4*       op = (float4*)(out + (size_t)bc * HW * HW);
    float4 v[4]; int f[4]; bool valid[4];
    #pragma unroll
    for (int k = 0; k < 4; ++k) {
        f[k] = tid + 256 * k;
        valid[k] = (f[k] < 784);
        if (valid[k]) v[k] = xp[f[k]];
    }
    #pragma unroll
    for (int k = 0; k < 4; ++k) {
        if (valid[k]) {
            int hrow = f[k] / 14;
            int c4   = f[k] - hrow * 14;
            float s = sca[hrow];
            float4 w4 = ((const float4*)saw)[c4];
            float4 o = v[k];
            o.x *= s * w4.x;
            o.y *= s * w4.y;
            o.z *= s * w4.z;
            o.w *= s * w4.w;
            op[f[k]] = o;
        }
    }
}

// ---------------- launch ---------------------------------------------------
extern "C" void kernel_launch(void* const* d_in, const int* in_sizes, int n_in,
                              void* d_out, int out_size) {
    const float* x  = (const float*)d_in[0];
    const float* w3 = (const float*)d_in[1];
    const float* b3 = (const float*)d_in[2];
    const float* w5 = (const float*)d_in[3];
    const float* b5 = (const float*)d_in[4];
    const float* w7 = (const float*)d_in[5];
    const float* b7 = (const float*)d_in[6];
    const float* w9 = (const float*)d_in[7];
    const float* b9 = (const float*)d_in[8];
    const float* nhs = (const float*)d_in[9];
    const float* nhb = (const float*)d_in[10];
    const float* nws = (const float*)d_in[11];
    const float* nwb = (const float*)d_in[12];
    const float* ns  = (const float*)d_in[13];
    const float* nb  = (const float*)d_in[14];
    const float* qw  = (const float*)d_in[15];
    const float* kw  = (const float*)d_in[16];
    const float* vw  = (const float*)d_in[17];
    float* out = (float*)d_out;

    k_means_sa<<<BC, 256>>>(x, w3, b3, w5, b5, w7, b7, w9, b9, nhs, nhb, nws, nwb);
    k_pool_attn<<<BC, 256>>>(x, ns, nb, qw, kw, vw);
    k_final<<<BC, 256>>>(x, out);
}

// round 7
// speedup vs baseline: 1.3180x; 1.3180x over previous
#include <cuda_runtime.h>
#include <math.h>

#define B 32
#define C 256
#define HW 56
#define BC (B*C)
#define POOL 7
#define NN 64
#define HEADS 8
#define HD 32
#define EPS 1e-5f

// ---------------- scratch ----------------
__device__ float g_mean_h[BC * HW];
__device__ float g_mean_w[BC * HW];
__device__ float g_attn_h[BC * HW];
__device__ float g_attn_w[BC * HW];
__device__ float g_pooled[BC * NN];
__device__ float g_bsum[B];
__device__ float g_bsumsq[B];
__device__ float g_ca[BC];

// ---------------- kernel 1: row & col means of each 56x56 plane ------------
// All 8 warps participate in the reduction tail: warp w -> rows/cols 7w..7w+6
__global__ __launch_bounds__(256) void k_means(const float* __restrict__ x) {
    __shared__ float sp[HW][HW + 1];
    int bc = blockIdx.x, tid = threadIdx.x;
    if (tid == 0 && bc < B) { g_bsum[bc] = 0.f; g_bsumsq[bc] = 0.f; }
    const float4* xp = (const float4*)(x + (size_t)bc * HW * HW);
    #pragma unroll
    for (int k = 0; k < 4; ++k) {
        int f = tid + 256 * k;
        if (f < 784) {
            float4 v = xp[f];
            int r = f / 14, c = (f - r * 14) * 4;
            sp[r][c]     = v.x;
            sp[r][c + 1] = v.y;
            sp[r][c + 2] = v.z;
            sp[r][c + 3] = v.w;
        }
    }
    __syncthreads();
    int lane = tid & 31, w = tid >> 5;
    #pragma unroll
    for (int i = 0; i < 7; ++i) {
        int r = w * 7 + i;
        float rv = sp[r][lane] + (lane < 24 ? sp[r][lane + 32] : 0.f);
        float cv = sp[lane][r] + (lane < 24 ? sp[lane + 32][r] : 0.f);
        #pragma unroll
        for (int o = 16; o; o >>= 1) {
            rv += __shfl_xor_sync(~0u, rv, o);
            cv += __shfl_xor_sync(~0u, cv, o);
        }
        if (lane == 0) {
            g_mean_h[bc * HW + r] = rv * (1.f / 56.f);
            g_mean_w[bc * HW + r] = cv * (1.f / 56.f);
        }
    }
}

// ---------------- kernel 2: sa_branch (dwconv -> GN(4) -> sigmoid) ---------
// grid (group=4, batch=32, branch=2), block 512. float4 I/O, conv in regs.
__global__ __launch_bounds__(512) void k_sa(
    const float* __restrict__ w3, const float* __restrict__ b3,
    const float* __restrict__ w5, const float* __restrict__ b5,
    const float* __restrict__ w7, const float* __restrict__ b7,
    const float* __restrict__ w9, const float* __restrict__ b9,
    const float* __restrict__ sh, const float* __restrict__ bh,
    const float* __restrict__ sw, const float* __restrict__ bw)
{
    __shared__ __align__(16) float sin_[64 * HW];   // 3584 floats
    __shared__ float r1[16], r2[16], sstat[2];

    int g  = blockIdx.x;
    int b  = blockIdx.y;
    int br = blockIdx.z;
    const float* in  = (br == 0) ? g_mean_h : g_mean_w;
    float*       out = (br == 0) ? g_attn_h : g_attn_w;
    const float* sc  = (br == 0) ? sh : sw;
    const float* bi  = (br == 0) ? bh : bw;
    const float* wf; const float* bf; int ksz;
    if (g == 0)      { wf = w3; bf = b3; ksz = 3; }
    else if (g == 1) { wf = w5; bf = b5; ksz = 5; }
    else if (g == 2) { wf = w7; bf = b7; ksz = 7; }
    else             { wf = w9; bf = b9; ksz = 9; }
    int pad = ksz >> 1;

    int tid = threadIdx.x;
    size_t base = ((size_t)b * C + g * 64) * HW;     // multiple of 3584 -> 16B aligned
    const float4* in4 = (const float4*)(in + base);
    float4*       out4 = (float4*)(out + base);
    #pragma unroll
    for (int k = 0; k < 2; ++k) {
        int f = tid + 512 * k;
        if (f < 896) ((float4*)sin_)[f] = in4[f];
    }
    __syncthreads();

    // conv: 2 float4 (8 outputs) per thread, kept in registers
    float o[8];
    float s = 0.f, ss = 0.f;
    int   cch[2];
    #pragma unroll
    for (int k = 0; k < 2; ++k) {
        int f = tid + 512 * k;
        if (f < 896) {
            int c  = f / 14;
            int l0 = (f - c * 14) * 4;
            cch[k] = c;
            const float* row = sin_ + c * HW;
            #pragma unroll
            for (int q = 0; q < 4; ++q) {
                int l = l0 + q;
                float acc = bf[c];
                for (int j = 0; j < ksz; ++j) {
                    int idx = l + j - pad;
                    if (idx >= 0 && idx < HW) acc = fmaf(wf[c * ksz + j], row[idx], acc);
                }
                o[k * 4 + q] = acc;
                s += acc; ss = fmaf(acc, acc, ss);
            }
        } else cch[k] = -1;
    }
    int lane = tid & 31, wid = tid >> 5;
    #pragma unroll
    for (int off = 16; off; off >>= 1) { s += __shfl_xor_sync(~0u, s, off); ss += __shfl_xor_sync(~0u, ss, off); }
    if (lane == 0) { r1[wid] = s; r2[wid] = ss; }
    __syncthreads();
    if (tid == 0) {
        float a = 0.f, bs2 = 0.f;
        #pragma unroll
        for (int w = 0; w < 16; ++w) { a += r1[w]; bs2 += r2[w]; }
        float mean = a * (1.f / 3584.f);
        float var  = bs2 * (1.f / 3584.f) - mean * mean;
        sstat[0] = mean;
        sstat[1] = rsqrtf(var + EPS);
    }
    __syncthreads();
    float mean = sstat[0], rstd = sstat[1];
    #pragma unroll
    for (int k = 0; k < 2; ++k) {
        if (cch[k] >= 0) {
            int f = tid + 512 * k;
            int cg = g * 64 + cch[k];
            float a_ = rstd * sc[cg], b_ = bi[cg] - mean * a_;
            float4 v;
            v.x = 1.f / (1.f + __expf(-(o[k*4+0] * a_ + b_)));
            v.y = 1.f / (1.f + __expf(-(o[k*4+1] * a_ + b_)));
            v.z = 1.f / (1.f + __expf(-(o[k*4+2] * a_ + b_)));
            v.w = 1.f / (1.f + __expf(-(o[k*4+3] * a_ + b_)));
            out4[f] = v;
        }
    }
}

// ---------------- kernel 3: pooled xg + per-batch stats --------------------
// pooling tail: 4 threads/cell (all 256 threads active), unrolled rows
__global__ __launch_bounds__(256) void k_pool(const float* __restrict__ x) {
    __shared__ float sp[HW][HW + 1];
    __shared__ float sah[HW], saw[HW];
    __shared__ float rs_[8], rss_[8];
    int bc = blockIdx.x, tid = threadIdx.x;
    int b = bc >> 8;
    if (tid < HW) { sah[tid] = g_attn_h[bc * HW + tid]; saw[tid] = g_attn_w[bc * HW + tid]; }
    __syncthreads();
    const float4* xp = (const float4*)(x + (size_t)bc * HW * HW);
    #pragma unroll
    for (int k = 0; k < 4; ++k) {
        int f = tid + 256 * k;
        if (f < 784) {
            float4 v = xp[f];
            int r = f / 14, c = (f - r * 14) * 4;
            float a = sah[r];
            sp[r][c]     = v.x * a * saw[c];
            sp[r][c + 1] = v.y * a * saw[c + 1];
            sp[r][c + 2] = v.z * a * saw[c + 2];
            sp[r][c + 3] = v.w * a * saw[c + 3];
        }
    }
    __syncthreads();
    // 4 threads per pooled cell; sub handles rows {sub, sub+4} of 7x7 window
    int cell = tid >> 2, sub = tid & 3;
    int pi = cell >> 3, pj = cell & 7;
    const float* rowA = &sp[POOL * pi + sub][POOL * pj];
    float sum = 0.f;
    #pragma unroll
    for (int v = 0; v < POOL; ++v) sum += rowA[v];
    if (sub < 3) {
        const float* rowB = &sp[POOL * pi + sub + 4][POOL * pj];
        #pragma unroll
        for (int v = 0; v < POOL; ++v) sum += rowB[v];
    }
    sum += __shfl_xor_sync(~0u, sum, 1);
    sum += __shfl_xor_sync(~0u, sum, 2);
    float pv = 0.f;
    if (sub == 0) {
        pv = sum * (1.f / 49.f);
        g_pooled[bc * NN + cell] = pv;
    }
    float s = pv, ss = pv * pv;
    #pragma unroll
    for (int o = 16; o; o >>= 1) { s += __shfl_xor_sync(~0u, s, o); ss += __shfl_xor_sync(~0u, ss, o); }
    int lane = tid & 31, wid = tid >> 5;
    if (lane == 0) { rs_[wid] = s; rss_[wid] = ss; }
    __syncthreads();
    if (tid == 0) {
        float a = 0.f, c2 = 0.f;
        #pragma unroll
        for (int w = 0; w < 8; ++w) { a += rs_[w]; c2 += rss_[w]; }
        atomicAdd(&g_bsum[b],   a);
        atomicAdd(&g_bsumsq[b], c2);
    }
}

// ---------------- kernel 4: attention -> channel gate ----------------------
// grid (head=8, batch=32), block 256. Row stride 68 floats (17 float4).
__global__ __launch_bounds__(256) void k_attn(
    const float* __restrict__ ns, const float* __restrict__ nb,
    const float* __restrict__ qw, const float* __restrict__ kw,
    const float* __restrict__ vw)
{
    __shared__ __align__(16) float xs[HD * 68];
    __shared__ float svbar[HD];
    int h = blockIdx.x, b = blockIdx.y;
    float bs = g_bsum[b], bss = g_bsumsq[b];
    float mu = bs * (1.f / 16384.f);
    float var = bss * (1.f / 16384.f) - mu * mu;
    float rstd = rsqrtf(var + EPS);
    const float4* p4 = (const float4*)(g_pooled + ((size_t)b * C + h * HD) * NN);
    int tid = threadIdx.x;
    #pragma unroll
    for (int k = 0; k < 2; ++k) {
        int f = tid + 256 * k;            // 0..511
        float4 v = p4[f];
        int e = f >> 4;                    // 16 float4 per row
        int c = h * HD + e;
        float a_ = rstd * ns[c], b_ = nb[c] - mu * a_;
        v.x = v.x * a_ + b_;
        v.y = v.y * a_ + b_;
        v.z = v.z * a_ + b_;
        v.w = v.w * a_ + b_;
        ((float4*)xs)[e * 17 + (f & 15)] = v;
    }
    __syncthreads();

    int wi = tid >> 5, lane = tid & 31;
    {
        float sv[4];
        #pragma unroll
        for (int dd = 0; dd < 4; ++dd) {
            int row = wi * 4 + dd;
            sv[dd] = xs[row * 68 + lane] + xs[row * 68 + lane + 32];
        }
        #pragma unroll
        for (int o = 16; o; o >>= 1)
            #pragma unroll
            for (int dd = 0; dd < 4; ++dd)
                sv[dd] += __shfl_xor_sync(~0u, sv[dd], o);
        if (lane == 0) {
            #pragma unroll
            for (int dd = 0; dd < 4; ++dd) {
                int row = wi * 4 + dd;
                svbar[row] = sv[dd] * (1.f / 64.f) * vw[h * HD + row];
            }
        }
    }
    __syncthreads();

    float kwe = kw[h * HD + lane];
    float vb  = svbar[lane];
    const float scale = 0.17677669529663687f;  // 32^-0.5
    int d0 = wi * 4;
    const float4* xs4 = (const float4*)xs;

    float acc[4];
    #pragma unroll
    for (int dd = 0; dd < 4; ++dd) acc[dd] = 0.f;
    #pragma unroll
    for (int j = 0; j < 16; ++j) {
        float4 t = xs4[lane * 17 + j];          // conflict-free LDS.128
        #pragma unroll
        for (int dd = 0; dd < 4; ++dd) {
            float4 q = xs4[(d0 + dd) * 17 + j]; // broadcast LDS.128
            acc[dd] = fmaf(t.x, q.x, acc[dd]);
            acc[dd] = fmaf(t.y, q.y, acc[dd]);
            acc[dd] = fmaf(t.z, q.z, acc[dd]);
            acc[dd] = fmaf(t.w, q.w, acc[dd]);
        }
    }
    float sarr[4];
    #pragma unroll
    for (int dd = 0; dd < 4; ++dd)
        sarr[dd] = acc[dd] * qw[h * HD + d0 + dd] * kwe * scale;

    float m[4], pe[4], Z[4], num[4];
    #pragma unroll
    for (int dd = 0; dd < 4; ++dd) m[dd] = sarr[dd];
    #pragma unroll
    for (int o = 16; o; o >>= 1)
        #pragma unroll
        for (int dd = 0; dd < 4; ++dd)
            m[dd] = fmaxf(m[dd], __shfl_xor_sync(~0u, m[dd], o));
    #pragma unroll
    for (int dd = 0; dd < 4; ++dd) {
        pe[dd]  = __expf(sarr[dd] - m[dd]);
        Z[dd]   = pe[dd];
        num[dd] = pe[dd] * vb;
    }
    #pragma unroll
    for (int o = 16; o; o >>= 1)
        #pragma unroll
        for (int dd = 0; dd < 4; ++dd) {
            Z[dd]   += __shfl_xor_sync(~0u, Z[dd], o);
            num[dd] += __shfl_xor_sync(~0u, num[dd], o);
        }
    if (lane == 0) {
        #pragma unroll
        for (int dd = 0; dd < 4; ++dd)
            g_ca[b * C + h * HD + d0 + dd] = 1.f / (1.f + __expf(-(num[dd] / Z[dd])));
    }
}

// ---------------- kernel 5: out = ca * x * ah * aw -------------------------
__global__ __launch_bounds__(256) void k_final(const float* __restrict__ x,
                                               float* __restrict__ out) {
    __shared__ float sca[HW], saw[HW];
    int bc = blockIdx.x, tid = threadIdx.x;
    float ca = g_ca[bc];
    if (tid < HW)                     sca[tid] = ca * g_attn_h[bc * HW + tid];
    else if (tid >= 64 && tid < 120)  saw[tid - 64] = g_attn_w[bc * HW + tid - 64];
    __syncthreads();
    const float4* xp = (const float4*)(x + (size_t)bc * HW * HW);
    float4*       op = (float4*)(out + (size_t)bc * HW * HW);
    float4 v[4]; int f[4]; bool valid[4];
    #pragma unroll
    for (int k = 0; k < 4; ++k) {
        f[k] = tid + 256 * k;
        valid[k] = (f[k] < 784);
        if (valid[k]) v[k] = xp[f[k]];
    }
    #pragma unroll
    for (int k = 0; k < 4; ++k) {
        if (valid[k]) {
            int hrow = f[k] / 14;
            int w4   = (f[k] - hrow * 14) * 4;
            float s = sca[hrow];
            float4 o = v[k];
            o.x *= s * saw[w4 + 0];
            o.y *= s * saw[w4 + 1];
            o.z *= s * saw[w4 + 2];
            o.w *= s * saw[w4 + 3];
            op[f[k]] = o;
        }
    }
}

// ---------------- launch ---------------------------------------------------
extern "C" void kernel_launch(void* const* d_in, const int* in_sizes, int n_in,
                              void* d_out, int out_size) {
    const float* x  = (const float*)d_in[0];
    const float* w3 = (const float*)d_in[1];
    const float* b3 = (const float*)d_in[2];
    const float* w5 = (const float*)d_in[3];
    const float* b5 = (const float*)d_in[4];
    const float* w7 = (const float*)d_in[5];
    const float* b7 = (const float*)d_in[6];
    const float* w9 = (const float*)d_in[7];
    const float* b9 = (const float*)d_in[8];
    const float* nhs = (const float*)d_in[9];
    const float* nhb = (const float*)d_in[10];
    const float* nws = (const float*)d_in[11];
    const float* nwb = (const float*)d_in[12];
    const float* ns  = (const float*)d_in[13];
    const float* nb  = (const float*)d_in[14];
    const float* qw  = (const float*)d_in[15];
    const float* kw  = (const float*)d_in[16];
    const float* vw  = (const float*)d_in[17];
    float* out = (float*)d_out;

    k_means<<<BC, 256>>>(x);
    k_sa<<<dim3(4, B, 2), 512>>>(w3, b3, w5, b5, w7, b7, w9, b9, nhs, nhb, nws, nwb);
    k_pool<<<BC, 256>>>(x);
    k_attn<<<dim3(HEADS, B), 256>>>(ns, nb, qw, kw, vw);
    k_final<<<BC, 256>>>(x, out);
}

// round 8
// speedup vs baseline: 1.6925x; 1.2841x over previous
#include <cuda_runtime.h>
#include <math.h>

#define B 32
#define C 256
#define HW 56
#define BC (B*C)
#define POOL 7
#define NN 64
#define HEADS 8
#define HD 32
#define EPS 1e-5f

// ---------------- scratch ----------------
__device__ float g_mean_h[BC * HW];
__device__ float g_mean_w[BC * HW];
__device__ float g_attn_h[BC * HW];
__device__ float g_attn_w[BC * HW];
__device__ float g_pooled[BC * NN];
__device__ float g_bsum[B];
__device__ float g_bsumsq[B];
__device__ float g_ca[BC];

// ---------------- kernel 1: row & col means of each 56x56 plane ------------
__global__ __launch_bounds__(256) void k_means(const float* __restrict__ x) {
    __shared__ float sp[HW][HW + 1];
    int bc = blockIdx.x, tid = threadIdx.x;
    if (tid == 0 && bc < B) { g_bsum[bc] = 0.f; g_bsumsq[bc] = 0.f; }
    const float4* xp = (const float4*)(x + (size_t)bc * HW * HW);
    #pragma unroll
    for (int k = 0; k < 4; ++k) {
        int f = tid + 256 * k;
        if (f < 784) {
            float4 v = xp[f];
            int r = f / 14, c = (f - r * 14) * 4;
            sp[r][c]     = v.x;
            sp[r][c + 1] = v.y;
            sp[r][c + 2] = v.z;
            sp[r][c + 3] = v.w;
        }
    }
    __syncthreads();
    if (tid < HW) {
        float rs = 0.f, cs = 0.f;
        #pragma unroll
        for (int w = 0; w < HW; ++w) { rs += sp[tid][w]; cs += sp[w][tid]; }
        g_mean_h[bc * HW + tid] = rs * (1.f / 56.f);
        g_mean_w[bc * HW + tid] = cs * (1.f / 56.f);
    }
}

// ---------------- kernel 2: sa_branch (dwconv -> GN(4) -> sigmoid) ---------
// grid (group=4, batch=32, branch=2), block 512. float4 I/O, conv in regs.
__global__ __launch_bounds__(512) void k_sa(
    const float* __restrict__ w3, const float* __restrict__ b3,
    const float* __restrict__ w5, const float* __restrict__ b5,
    const float* __restrict__ w7, const float* __restrict__ b7,
    const float* __restrict__ w9, const float* __restrict__ b9,
    const float* __restrict__ sh, const float* __restrict__ bh,
    const float* __restrict__ sw, const float* __restrict__ bw)
{
    __shared__ __align__(16) float sin_[64 * HW];   // 3584 floats
    __shared__ float r1[16], r2[16], sstat[2];

    int g  = blockIdx.x;
    int b  = blockIdx.y;
    int br = blockIdx.z;
    const float* in  = (br == 0) ? g_mean_h : g_mean_w;
    float*       out = (br == 0) ? g_attn_h : g_attn_w;
    const float* sc  = (br == 0) ? sh : sw;
    const float* bi  = (br == 0) ? bh : bw;
    const float* wf; const float* bf; int ksz;
    if (g == 0)      { wf = w3; bf = b3; ksz = 3; }
    else if (g == 1) { wf = w5; bf = b5; ksz = 5; }
    else if (g == 2) { wf = w7; bf = b7; ksz = 7; }
    else             { wf = w9; bf = b9; ksz = 9; }
    int pad = ksz >> 1;

    int tid = threadIdx.x;
    size_t base = ((size_t)b * C + g * 64) * HW;     // multiple of 3584 -> 16B aligned
    const float4* in4 = (const float4*)(in + base);
    float4*       out4 = (float4*)(out + base);
    #pragma unroll
    for (int k = 0; k < 2; ++k) {
        int f = tid + 512 * k;
        if (f < 896) ((float4*)sin_)[f] = in4[f];
    }
    __syncthreads();

    float o[8];
    float s = 0.f, ss = 0.f;
    int   cch[2];
    #pragma unroll
    for (int k = 0; k < 2; ++k) {
        int f = tid + 512 * k;
        if (f < 896) {
            int c  = f / 14;
            int l0 = (f - c * 14) * 4;
            cch[k] = c;
            const float* row = sin_ + c * HW;
            #pragma unroll
            for (int q = 0; q < 4; ++q) {
                int l = l0 + q;
                float acc = bf[c];
                for (int j = 0; j < ksz; ++j) {
                    int idx = l + j - pad;
                    if (idx >= 0 && idx < HW) acc = fmaf(wf[c * ksz + j], row[idx], acc);
                }
                o[k * 4 + q] = acc;
                s += acc; ss = fmaf(acc, acc, ss);
            }
        } else cch[k] = -1;
    }
    int lane = tid & 31, wid = tid >> 5;
    #pragma unroll
    for (int off = 16; off; off >>= 1) { s += __shfl_xor_sync(~0u, s, off); ss += __shfl_xor_sync(~0u, ss, off); }
    if (lane == 0) { r1[wid] = s; r2[wid] = ss; }
    __syncthreads();
    if (tid == 0) {
        float a = 0.f, bs2 = 0.f;
        #pragma unroll
        for (int w = 0; w < 16; ++w) { a += r1[w]; bs2 += r2[w]; }
        float mean = a * (1.f / 3584.f);
        float var  = bs2 * (1.f / 3584.f) - mean * mean;
        sstat[0] = mean;
        sstat[1] = rsqrtf(var + EPS);
    }
    __syncthreads();
    float mean = sstat[0], rstd = sstat[1];
    #pragma unroll
    for (int k = 0; k < 2; ++k) {
        if (cch[k] >= 0) {
            int f = tid + 512 * k;
            int cg = g * 64 + cch[k];
            float a_ = rstd * sc[cg], b_ = bi[cg] - mean * a_;
            float4 v;
            v.x = 1.f / (1.f + __expf(-(o[k*4+0] * a_ + b_)));
            v.y = 1.f / (1.f + __expf(-(o[k*4+1] * a_ + b_)));
            v.z = 1.f / (1.f + __expf(-(o[k*4+2] * a_ + b_)));
            v.w = 1.f / (1.f + __expf(-(o[k*4+3] * a_ + b_)));
            out4[f] = v;
        }
    }
}

// ---------------- kernel 3: pooled xg + per-batch stats --------------------
__global__ __launch_bounds__(256) void k_pool(const float* __restrict__ x) {
    __shared__ float sp[HW][HW + 1];
    __shared__ float sah[HW], saw[HW];
    __shared__ float rs_[2], rss_[2];
    int bc = blockIdx.x, tid = threadIdx.x;
    int b = bc >> 8;
    if (tid < HW) { sah[tid] = g_attn_h[bc * HW + tid]; saw[tid] = g_attn_w[bc * HW + tid]; }
    __syncthreads();
    const float4* xp = (const float4*)(x + (size_t)bc * HW * HW);
    #pragma unroll
    for (int k = 0; k < 4; ++k) {
        int f = tid + 256 * k;
        if (f < 784) {
            float4 v = xp[f];
            int r = f / 14, c = (f - r * 14) * 4;
            float a = sah[r];
            sp[r][c]     = v.x * a * saw[c];
            sp[r][c + 1] = v.y * a * saw[c + 1];
            sp[r][c + 2] = v.z * a * saw[c + 2];
            sp[r][c + 3] = v.w * a * saw[c + 3];
        }
    }
    __syncthreads();
    float pv = 0.f;
    if (tid < NN) {
        int i = tid >> 3, j = tid & 7;
        float sum = 0.f;
        #pragma unroll
        for (int u = 0; u < POOL; ++u)
            #pragma unroll
            for (int v = 0; v < POOL; ++v)
                sum += sp[POOL * i + u][POOL * j + v];
        pv = sum * (1.f / 49.f);
        g_pooled[bc * NN + tid] = pv;
    }
    if (tid < NN) {
        float s = pv, ss = pv * pv;
        #pragma unroll
        for (int o = 16; o; o >>= 1) { s += __shfl_xor_sync(~0u, s, o); ss += __shfl_xor_sync(~0u, ss, o); }
        int lane = tid & 31, wid = tid >> 5;
        if (lane == 0) { rs_[wid] = s; rss_[wid] = ss; }
    }
    __syncthreads();
    if (tid == 0) {
        atomicAdd(&g_bsum[b],   rs_[0] + rs_[1]);
        atomicAdd(&g_bsumsq[b], rss_[0] + rss_[1]);
    }
}

// ---------------- kernel 4: attention -> channel gate ----------------------
// grid (head=8, batch=32), block 256. Row stride 68 floats (17 float4).
__global__ __launch_bounds__(256) void k_attn(
    const float* __restrict__ ns, const float* __restrict__ nb,
    const float* __restrict__ qw, const float* __restrict__ kw,
    const float* __restrict__ vw)
{
    __shared__ __align__(16) float xs[HD * 68];
    __shared__ float svbar[HD];
    int h = blockIdx.x, b = blockIdx.y;
    float bs = g_bsum[b], bss = g_bsumsq[b];
    float mu = bs * (1.f / 16384.f);
    float var = bss * (1.f / 16384.f) - mu * mu;
    float rstd = rsqrtf(var + EPS);
    const float4* p4 = (const float4*)(g_pooled + ((size_t)b * C + h * HD) * NN);
    int tid = threadIdx.x;
    #pragma unroll
    for (int k = 0; k < 2; ++k) {
        int f = tid + 256 * k;            // 0..511
        float4 v = p4[f];
        int e = f >> 4;                    // 16 float4 per row
        int c = h * HD + e;
        float a_ = rstd * ns[c], b_ = nb[c] - mu * a_;
        v.x = v.x * a_ + b_;
        v.y = v.y * a_ + b_;
        v.z = v.z * a_ + b_;
        v.w = v.w * a_ + b_;
        ((float4*)xs)[e * 17 + (f & 15)] = v;
    }
    __syncthreads();

    int wi = tid >> 5, lane = tid & 31;
    {
        float sv[4];
        #pragma unroll
        for (int dd = 0; dd < 4; ++dd) {
            int row = wi * 4 + dd;
            sv[dd] = xs[row * 68 + lane] + xs[row * 68 + lane + 32];
        }
        #pragma unroll
        for (int o = 16; o; o >>= 1)
            #pragma unroll
            for (int dd = 0; dd < 4; ++dd)
                sv[dd] += __shfl_xor_sync(~0u, sv[dd], o);
        if (lane == 0) {
            #pragma unroll
            for (int dd = 0; dd < 4; ++dd) {
                int row = wi * 4 + dd;
                svbar[row] = sv[dd] * (1.f / 64.f) * vw[h * HD + row];
            }
        }
    }
    __syncthreads();

    float kwe = kw[h * HD + lane];
    float vb  = svbar[lane];
    const float scale = 0.17677669529663687f;  // 32^-0.5
    int d0 = wi * 4;
    const float4* xs4 = (const float4*)xs;

    float acc[4];
    #pragma unroll
    for (int dd = 0; dd < 4; ++dd) acc[dd] = 0.f;
    #pragma unroll
    for (int j = 0; j < 16; ++j) {
        float4 t = xs4[lane * 17 + j];          // conflict-free LDS.128
        #pragma unroll
        for (int dd = 0; dd < 4; ++dd) {
            float4 q = xs4[(d0 + dd) * 17 + j]; // broadcast LDS.128
            acc[dd] = fmaf(t.x, q.x, acc[dd]);
            acc[dd] = fmaf(t.y, q.y, acc[dd]);
            acc[dd] = fmaf(t.z, q.z, acc[dd]);
            acc[dd] = fmaf(t.w, q.w, acc[dd]);
        }
    }
    float sarr[4];
    #pragma unroll
    for (int dd = 0; dd < 4; ++dd)
        sarr[dd] = acc[dd] * qw[h * HD + d0 + dd] * kwe * scale;

    float m[4], pe[4], Z[4], num[4];
    #pragma unroll
    for (int dd = 0; dd < 4; ++dd) m[dd] = sarr[dd];
    #pragma unroll
    for (int o = 16; o; o >>= 1)
        #pragma unroll
        for (int dd = 0; dd < 4; ++dd)
            m[dd] = fmaxf(m[dd], __shfl_xor_sync(~0u, m[dd], o));
    #pragma unroll
    for (int dd = 0; dd < 4; ++dd) {
        pe[dd]  = __expf(sarr[dd] - m[dd]);
        Z[dd]   = pe[dd];
        num[dd] = pe[dd] * vb;
    }
    #pragma unroll
    for (int o = 16; o; o >>= 1)
        #pragma unroll
        for (int dd = 0; dd < 4; ++dd) {
            Z[dd]   += __shfl_xor_sync(~0u, Z[dd], o);
            num[dd] += __shfl_xor_sync(~0u, num[dd], o);
        }
    if (lane == 0) {
        #pragma unroll
        for (int dd = 0; dd < 4; ++dd)
            g_ca[b * C + h * HD + d0 + dd] = 1.f / (1.f + __expf(-(num[dd] / Z[dd])));
    }
}

// ---------------- kernel 5: out = ca * x * ah * aw  (2 planes/block) -------
// Planes are contiguous: pair spans 1568 float4. 7 front-batched LDG.128.
__global__ __launch_bounds__(256) void k_final(const float* __restrict__ x,
                                               float* __restrict__ out) {
    __shared__ float sca[2][HW];
    __shared__ __align__(16) float saw[2][HW];
    int pair = blockIdx.x, tid = threadIdx.x;
    int bc0 = pair * 2;
    // warp 0-1 stage plane0 vectors, warp 4-5 stage plane1 (independent warps)
    if (tid < HW) {
        sca[0][tid] = g_ca[bc0]     * g_attn_h[bc0 * HW + tid];
        saw[0][tid] = g_attn_w[bc0 * HW + tid];
    } else if (tid >= 128 && tid < 128 + HW) {
        int t = tid - 128;
        sca[1][t] = g_ca[bc0 + 1] * g_attn_h[(bc0 + 1) * HW + t];
        saw[1][t] = g_attn_w[(bc0 + 1) * HW + t];
    }
    __syncthreads();
    const float4* xp = (const float4*)(x + (size_t)bc0 * HW * HW);
    float4*       op = (float4*)(out + (size_t)bc0 * HW * HW);
    // 2*784 = 1568 float4; 7 per thread, front-batched for MLP
    float4 v[7];
    #pragma unroll
    for (int k = 0; k < 7; ++k) {
        int f = tid + 256 * k;
        if (f < 1568) v[k] = xp[f];
    }
    #pragma unroll
    for (int k = 0; k < 7; ++k) {
        int f = tid + 256 * k;
        if (f < 1568) {
            int pl   = (f >= 784);
            int loc  = f - 784 * pl;
            int hrow = loc / 14;
            int c4   = loc - hrow * 14;
            float s = sca[pl][hrow];
            float4 w4 = ((const float4*)saw[pl])[c4];
            float4 o = v[k];
            o.x *= s * w4.x;
            o.y *= s * w4.y;
            o.z *= s * w4.z;
            o.w *= s * w4.w;
            op[f] = o;
        }
    }
}

// ---------------- launch ---------------------------------------------------
extern "C" void kernel_launch(void* const* d_in, const int* in_sizes, int n_in,
                              void* d_out, int out_size) {
    const float* x  = (const float*)d_in[0];
    const float* w3 = (const float*)d_in[1];
    const float* b3 = (const float*)d_in[2];
    const float* w5 = (const float*)d_in[3];
    const float* b5 = (const float*)d_in[4];
    const float* w7 = (const float*)d_in[5];
    const float* b7 = (const float*)d_in[6];
    const float* w9 = (const float*)d_in[7];
    const float* b9 = (const float*)d_in[8];
    const float* nhs = (const float*)d_in[9];
    const float* nhb = (const float*)d_in[10];
    const float* nws = (const float*)d_in[11];
    const float* nwb = (const float*)d_in[12];
    const float* ns  = (const float*)d_in[13];
    const float* nb  = (const float*)d_in[14];
    const float* qw  = (const float*)d_in[15];
    const float* kw  = (const float*)d_in[16];
    const float* vw  = (const float*)d_in[17];
    float* out = (float*)d_out;

    k_means<<<BC, 256>>>(x);
    k_sa<<<dim3(4, B, 2), 512>>>(w3, b3, w5, b5, w7, b7, w9, b9, nhs, nhb, nws, nwb);
    k_pool<<<BC, 256>>>(x);
    k_attn<<<dim3(HEADS, B), 256>>>(ns, nb, qw, kw, vw);
    k_final<<<BC / 2, 256>>>(x, out);
}

// round 9
// speedup vs baseline: 1.6983x; 1.0034x over previous
#include <cuda_runtime.h>
#include <math.h>

#define B 32
#define C 256
#define HW 56
#define BC (B*C)
#define POOL 7
#define NN 64
#define HEADS 8
#define HD 32
#define EPS 1e-5f

// ---------------- scratch ----------------
__device__ float g_mean_h[BC * HW];
__device__ float g_mean_w[BC * HW];
__device__ float g_attn_h[BC * HW];
__device__ float g_attn_w[BC * HW];
__device__ float g_pooled[BC * NN];
__device__ float g_bsum[B];
__device__ float g_bsumsq[B];
__device__ float g_ca[BC];

// ---------------- kernel 0: no-op (shifts ncu capture slot to k_pool) ------
__global__ void k_tag() {}

// ---------------- kernel 1: row & col means of each 56x56 plane ------------
__global__ __launch_bounds__(256) void k_means(const float* __restrict__ x) {
    __shared__ float sp[HW][HW + 1];
    int bc = blockIdx.x, tid = threadIdx.x;
    if (tid == 0 && bc < B) { g_bsum[bc] = 0.f; g_bsumsq[bc] = 0.f; }
    const float4* xp = (const float4*)(x + (size_t)bc * HW * HW);
    #pragma unroll
    for (int k = 0; k < 4; ++k) {
        int f = tid + 256 * k;
        if (f < 784) {
            float4 v = xp[f];
            int r = f / 14, c = (f - r * 14) * 4;
            sp[r][c]     = v.x;
            sp[r][c + 1] = v.y;
            sp[r][c + 2] = v.z;
            sp[r][c + 3] = v.w;
        }
    }
    __syncthreads();
    if (tid < HW) {
        float rs = 0.f, cs = 0.f;
        #pragma unroll
        for (int w = 0; w < HW; ++w) { rs += sp[tid][w]; cs += sp[w][tid]; }
        g_mean_h[bc * HW + tid] = rs * (1.f / 56.f);
        g_mean_w[bc * HW + tid] = cs * (1.f / 56.f);
    }
}

// ---------------- kernel 2: sa_branch (dwconv -> GN(4) -> sigmoid) ---------
// grid (group=4, batch=32, branch=2), block 512. float4 I/O, conv in regs.
__global__ __launch_bounds__(512) void k_sa(
    const float* __restrict__ w3, const float* __restrict__ b3,
    const float* __restrict__ w5, const float* __restrict__ b5,
    const float* __restrict__ w7, const float* __restrict__ b7,
    const float* __restrict__ w9, const float* __restrict__ b9,
    const float* __restrict__ sh, const float* __restrict__ bh,
    const float* __restrict__ sw, const float* __restrict__ bw)
{
    __shared__ __align__(16) float sin_[64 * HW];   // 3584 floats
    __shared__ float r1[16], r2[16], sstat[2];

    int g  = blockIdx.x;
    int b  = blockIdx.y;
    int br = blockIdx.z;
    const float* in  = (br == 0) ? g_mean_h : g_mean_w;
    float*       out = (br == 0) ? g_attn_h : g_attn_w;
    const float* sc  = (br == 0) ? sh : sw;
    const float* bi  = (br == 0) ? bh : bw;
    const float* wf; const float* bf; int ksz;
    if (g == 0)      { wf = w3; bf = b3; ksz = 3; }
    else if (g == 1) { wf = w5; bf = b5; ksz = 5; }
    else if (g == 2) { wf = w7; bf = b7; ksz = 7; }
    else             { wf = w9; bf = b9; ksz = 9; }
    int pad = ksz >> 1;

    int tid = threadIdx.x;
    size_t base = ((size_t)b * C + g * 64) * HW;     // multiple of 3584 -> 16B aligned
    const float4* in4 = (const float4*)(in + base);
    float4*       out4 = (float4*)(out + base);
    #pragma unroll
    for (int k = 0; k < 2; ++k) {
        int f = tid + 512 * k;
        if (f < 896) ((float4*)sin_)[f] = in4[f];
    }
    __syncthreads();

    float o[8];
    float s = 0.f, ss = 0.f;
    int   cch[2];
    #pragma unroll
    for (int k = 0; k < 2; ++k) {
        int f = tid + 512 * k;
        if (f < 896) {
            int c  = f / 14;
            int l0 = (f - c * 14) * 4;
            cch[k] = c;
            const float* row = sin_ + c * HW;
            #pragma unroll
            for (int q = 0; q < 4; ++q) {
                int l = l0 + q;
                float acc = bf[c];
                for (int j = 0; j < ksz; ++j) {
                    int idx = l + j - pad;
                    if (idx >= 0 && idx < HW) acc = fmaf(wf[c * ksz + j], row[idx], acc);
                }
                o[k * 4 + q] = acc;
                s += acc; ss = fmaf(acc, acc, ss);
            }
        } else cch[k] = -1;
    }
    int lane = tid & 31, wid = tid >> 5;
    #pragma unroll
    for (int off = 16; off; off >>= 1) { s += __shfl_xor_sync(~0u, s, off); ss += __shfl_xor_sync(~0u, ss, off); }
    if (lane == 0) { r1[wid] = s; r2[wid] = ss; }
    __syncthreads();
    if (tid == 0) {
        float a = 0.f, bs2 = 0.f;
        #pragma unroll
        for (int w = 0; w < 16; ++w) { a += r1[w]; bs2 += r2[w]; }
        float mean = a * (1.f / 3584.f);
        float var  = bs2 * (1.f / 3584.f) - mean * mean;
        sstat[0] = mean;
        sstat[1] = rsqrtf(var + EPS);
    }
    __syncthreads();
    float mean = sstat[0], rstd = sstat[1];
    #pragma unroll
    for (int k = 0; k < 2; ++k) {
        if (cch[k] >= 0) {
            int f = tid + 512 * k;
            int cg = g * 64 + cch[k];
            float a_ = rstd * sc[cg], b_ = bi[cg] - mean * a_;
            float4 v;
            v.x = 1.f / (1.f + __expf(-(o[k*4+0] * a_ + b_)));
            v.y = 1.f / (1.f + __expf(-(o[k*4+1] * a_ + b_)));
            v.z = 1.f / (1.f + __expf(-(o[k*4+2] * a_ + b_)));
            v.w = 1.f / (1.f + __expf(-(o[k*4+3] * a_ + b_)));
            out4[f] = v;
        }
    }
}

// ---------------- kernel 3: pooled xg + per-batch stats --------------------
// staged plane stride 60 floats (15 float4/row): STS.128 staging.
// pooling tail (64 threads x 49 LDS) conflict-free: banks (4i+7j)%32 distinct.
__global__ __launch_bounds__(256) void k_pool(const float* __restrict__ x) {
    __shared__ __align__(16) float sp[HW * 60];
    __shared__ __align__(16) float sah[HW], saw[HW];
    __shared__ float rs_[2], rss_[2];
    int bc = blockIdx.x, tid = threadIdx.x;
    int b = bc >> 8;
    if (tid < HW) { sah[tid] = g_attn_h[bc * HW + tid]; saw[tid] = g_attn_w[bc * HW + tid]; }
    __syncthreads();
    const float4* xp = (const float4*)(x + (size_t)bc * HW * HW);
    #pragma unroll
    for (int k = 0; k < 4; ++k) {
        int f = tid + 256 * k;
        if (f < 784) {
            float4 v = xp[f];
            int r = f / 14, c4 = f - r * 14;
            float a = sah[r];
            float4 w4 = ((const float4*)saw)[c4];
            float4 t;
            t.x = v.x * a * w4.x;
            t.y = v.y * a * w4.y;
            t.z = v.z * a * w4.z;
            t.w = v.w * a * w4.w;
            ((float4*)sp)[r * 15 + c4] = t;     // one STS.128
        }
    }
    __syncthreads();
    float pv = 0.f;
    if (tid < NN) {
        int i = tid >> 3, j = tid & 7;
        const float* base = sp + (POOL * i) * 60 + POOL * j;
        float sum = 0.f;
        #pragma unroll
        for (int u = 0; u < POOL; ++u)
            #pragma unroll
            for (int v = 0; v < POOL; ++v)
                sum += base[u * 60 + v];
        pv = sum * (1.f / 49.f);
        g_pooled[bc * NN + tid] = pv;
    }
    if (tid < NN) {
        float s = pv, ss = pv * pv;
        #pragma unroll
        for (int o = 16; o; o >>= 1) { s += __shfl_xor_sync(~0u, s, o); ss += __shfl_xor_sync(~0u, ss, o); }
        int lane = tid & 31, wid = tid >> 5;
        if (lane == 0) { rs_[wid] = s; rss_[wid] = ss; }
    }
    __syncthreads();
    if (tid == 0) {
        atomicAdd(&g_bsum[b],   rs_[0] + rs_[1]);
        atomicAdd(&g_bsumsq[b], rss_[0] + rss_[1]);
    }
}

// ---------------- kernel 4: attention -> channel gate ----------------------
// grid (head=8, batch=32), block 256. Row stride 68 floats (17 float4).
__global__ __launch_bounds__(256) void k_attn(
    const float* __restrict__ ns, const float* __restrict__ nb,
    const float* __restrict__ qw, const float* __restrict__ kw,
    const float* __restrict__ vw)
{
    __shared__ __align__(16) float xs[HD * 68];
    __shared__ float svbar[HD];
    int h = blockIdx.x, b = blockIdx.y;
    float bs = g_bsum[b], bss = g_bsumsq[b];
    float mu = bs * (1.f / 16384.f);
    float var = bss * (1.f / 16384.f) - mu * mu;
    float rstd = rsqrtf(var + EPS);
    const float4* p4 = (const float4*)(g_pooled + ((size_t)b * C + h * HD) * NN);
    int tid = threadIdx.x;
    #pragma unroll
    for (int k = 0; k < 2; ++k) {
        int f = tid + 256 * k;            // 0..511
        float4 v = p4[f];
        int e = f >> 4;                    // 16 float4 per row
        int c = h * HD + e;
        float a_ = rstd * ns[c], b_ = nb[c] - mu * a_;
        v.x = v.x * a_ + b_;
        v.y = v.y * a_ + b_;
        v.z = v.z * a_ + b_;
        v.w = v.w * a_ + b_;
        ((float4*)xs)[e * 17 + (f & 15)] = v;
    }
    __syncthreads();

    int wi = tid >> 5, lane = tid & 31;
    {
        float sv[4];
        #pragma unroll
        for (int dd = 0; dd < 4; ++dd) {
            int row = wi * 4 + dd;
            sv[dd] = xs[row * 68 + lane] + xs[row * 68 + lane + 32];
        }
        #pragma unroll
        for (int o = 16; o; o >>= 1)
            #pragma unroll
            for (int dd = 0; dd < 4; ++dd)
                sv[dd] += __shfl_xor_sync(~0u, sv[dd], o);
        if (lane == 0) {
            #pragma unroll
            for (int dd = 0; dd < 4; ++dd) {
                int row = wi * 4 + dd;
                svbar[row] = sv[dd] * (1.f / 64.f) * vw[h * HD + row];
            }
        }
    }
    __syncthreads();

    float kwe = kw[h * HD + lane];
    float vb  = svbar[lane];
    const float scale = 0.17677669529663687f;  // 32^-0.5
    int d0 = wi * 4;
    const float4* xs4 = (const float4*)xs;

    float acc[4];
    #pragma unroll
    for (int dd = 0; dd < 4; ++dd) acc[dd] = 0.f;
    #pragma unroll
    for (int j = 0; j < 16; ++j) {
        float4 t = xs4[lane * 17 + j];          // conflict-free LDS.128
        #pragma unroll
        for (int dd = 0; dd < 4; ++dd) {
            float4 q = xs4[(d0 + dd) * 17 + j]; // broadcast LDS.128
            acc[dd] = fmaf(t.x, q.x, acc[dd]);
            acc[dd] = fmaf(t.y, q.y, acc[dd]);
            acc[dd] = fmaf(t.z, q.z, acc[dd]);
            acc[dd] = fmaf(t.w, q.w, acc[dd]);
        }
    }
    float sarr[4];
    #pragma unroll
    for (int dd = 0; dd < 4; ++dd)
        sarr[dd] = acc[dd] * qw[h * HD + d0 + dd] * kwe * scale;

    float m[4], pe[4], Z[4], num[4];
    #pragma unroll
    for (int dd = 0; dd < 4; ++dd) m[dd] = sarr[dd];
    #pragma unroll
    for (int o = 16; o; o >>= 1)
        #pragma unroll
        for (int dd = 0; dd < 4; ++dd)
            m[dd] = fmaxf(m[dd], __shfl_xor_sync(~0u, m[dd], o));
    #pragma unroll
    for (int dd = 0; dd < 4; ++dd) {
        pe[dd]  = __expf(sarr[dd] - m[dd]);
        Z[dd]   = pe[dd];
        num[dd] = pe[dd] * vb;
    }
    #pragma unroll
    for (int o = 16; o; o >>= 1)
        #pragma unroll
        for (int dd = 0; dd < 4; ++dd) {
            Z[dd]   += __shfl_xor_sync(~0u, Z[dd], o);
            num[dd] += __shfl_xor_sync(~0u, num[dd], o);
        }
    if (lane == 0) {
        #pragma unroll
        for (int dd = 0; dd < 4; ++dd)
            g_ca[b * C + h * HD + d0 + dd] = 1.f / (1.f + __expf(-(num[dd] / Z[dd])));
    }
}

// ---------------- kernel 5: out = ca * x * ah * aw -------------------------
__global__ __launch_bounds__(256) void k_final(const float* __restrict__ x,
                                               float* __restrict__ out) {
    __shared__ float sca[HW], saw[HW];
    int bc = blockIdx.x, tid = threadIdx.x;
    float ca = g_ca[bc];
    if (tid < HW)                     sca[tid] = ca * g_attn_h[bc * HW + tid];
    else if (tid >= 64 && tid < 120)  saw[tid - 64] = g_attn_w[bc * HW + tid - 64];
    __syncthreads();
    const float4* xp = (const float4*)(x + (size_t)bc * HW * HW);
    float4*       op = (float4*)(out + (size_t)bc * HW * HW);
    float4 v[4]; int f[4]; bool valid[4];
    #pragma unroll
    for (int k = 0; k < 4; ++k) {
        f[k] = tid + 256 * k;
        valid[k] = (f[k] < 784);
        if (valid[k]) v[k] = xp[f[k]];
    }
    #pragma unroll
    for (int k = 0; k < 4; ++k) {
        if (valid[k]) {
            int hrow = f[k] / 14;
            int w4   = (f[k] - hrow * 14) * 4;
            float s = sca[hrow];
            float4 o = v[k];
            o.x *= s * saw[w4 + 0];
            o.y *= s * saw[w4 + 1];
            o.z *= s * saw[w4 + 2];
            o.w *= s * saw[w4 + 3];
            op[f[k]] = o;
        }
    }
}

// ---------------- launch ---------------------------------------------------
extern "C" void kernel_launch(void* const* d_in, const int* in_sizes, int n_in,
                              void* d_out, int out_size) {
    const float* x  = (const float*)d_in[0];
    const float* w3 = (const float*)d_in[1];
    const float* b3 = (const float*)d_in[2];
    const float* w5 = (const float*)d_in[3];
    const float* b5 = (const float*)d_in[4];
    const float* w7 = (const float*)d_in[5];
    const float* b7 = (const float*)d_in[6];
    const float* w9 = (const float*)d_in[7];
    const float* b9 = (const float*)d_in[8];
    const float* nhs = (const float*)d_in[9];
    const float* nhb = (const float*)d_in[10];
    const float* nws = (const float*)d_in[11];
    const float* nwb = (const float*)d_in[12];
    const float* ns  = (const float*)d_in[13];
    const float* nb  = (const float*)d_in[14];
    const float* qw  = (const float*)d_in[15];
    const float* kw  = (const float*)d_in[16];
    const float* vw  = (const float*)d_in[17];
    float* out = (float*)d_out;

    k_tag<<<1, 32>>>();   // shifts ncu's fixed capture slot onto k_pool
    k_means<<<BC, 256>>>(x);
    k_sa<<<dim3(4, B, 2), 512>>>(w3, b3, w5, b5, w7, b7, w9, b9, nhs, nhb, nws, nwb);
    k_pool<<<BC, 256>>>(x);
    k_attn<<<dim3(HEADS, B), 256>>>(ns, nb, qw, kw, vw);
    k_final<<<BC, 256>>>(x, out);
}

// round 10
// speedup vs baseline: 1.8294x; 1.0772x over previous
#include <cuda_runtime.h>
#include <math.h>

#define B 32
#define C 256
#define HW 56
#define BC (B*C)
#define POOL 7
#define NN 64
#define HEADS 8
#define HD 32
#define EPS 1e-5f

// ---------------- scratch ----------------
__device__ float g_mean_h[BC * HW];
__device__ float g_mean_w[BC * HW];
__device__ float g_attn_h[BC * HW];
__device__ float g_attn_w[BC * HW];
__device__ float g_pooled[BC * NN];
__device__ float g_bsum[B];
__device__ float g_bsumsq[B];
__device__ float g_ca[BC];

// ---------------- kernel 0: no-op (keeps ncu capture slot on k_pool) -------
__global__ void k_tag() {}

// ---------------- kernel 1: row & col means of each 56x56 plane ------------
__global__ __launch_bounds__(256) void k_means(const float* __restrict__ x) {
    __shared__ float sp[HW][HW + 1];
    int bc = blockIdx.x, tid = threadIdx.x;
    if (tid == 0 && bc < B) { g_bsum[bc] = 0.f; g_bsumsq[bc] = 0.f; }
    const float4* xp = (const float4*)(x + (size_t)bc * HW * HW);
    #pragma unroll
    for (int k = 0; k < 4; ++k) {
        int f = tid + 256 * k;
        if (f < 784) {
            float4 v = xp[f];
            int r = f / 14, c = (f - r * 14) * 4;
            sp[r][c]     = v.x;
            sp[r][c + 1] = v.y;
            sp[r][c + 2] = v.z;
            sp[r][c + 3] = v.w;
        }
    }
    __syncthreads();
    if (tid < HW) {
        float rs = 0.f, cs = 0.f;
        #pragma unroll
        for (int w = 0; w < HW; ++w) { rs += sp[tid][w]; cs += sp[w][tid]; }
        g_mean_h[bc * HW + tid] = rs * (1.f / 56.f);
        g_mean_w[bc * HW + tid] = cs * (1.f / 56.f);
    }
}

// ---------------- kernel 2: sa_branch (dwconv -> GN(4) -> sigmoid) ---------
__global__ __launch_bounds__(512) void k_sa(
    const float* __restrict__ w3, const float* __restrict__ b3,
    const float* __restrict__ w5, const float* __restrict__ b5,
    const float* __restrict__ w7, const float* __restrict__ b7,
    const float* __restrict__ w9, const float* __restrict__ b9,
    const float* __restrict__ sh, const float* __restrict__ bh,
    const float* __restrict__ sw, const float* __restrict__ bw)
{
    __shared__ __align__(16) float sin_[64 * HW];   // 3584 floats
    __shared__ float r1[16], r2[16], sstat[2];

    int g  = blockIdx.x;
    int b  = blockIdx.y;
    int br = blockIdx.z;
    const float* in  = (br == 0) ? g_mean_h : g_mean_w;
    float*       out = (br == 0) ? g_attn_h : g_attn_w;
    const float* sc  = (br == 0) ? sh : sw;
    const float* bi  = (br == 0) ? bh : bw;
    const float* wf; const float* bf; int ksz;
    if (g == 0)      { wf = w3; bf = b3; ksz = 3; }
    else if (g == 1) { wf = w5; bf = b5; ksz = 5; }
    else if (g == 2) { wf = w7; bf = b7; ksz = 7; }
    else             { wf = w9; bf = b9; ksz = 9; }
    int pad = ksz >> 1;

    int tid = threadIdx.x;
    size_t base = ((size_t)b * C + g * 64) * HW;
    const float4* in4 = (const float4*)(in + base);
    float4*       out4 = (float4*)(out + base);
    #pragma unroll
    for (int k = 0; k < 2; ++k) {
        int f = tid + 512 * k;
        if (f < 896) ((float4*)sin_)[f] = in4[f];
    }
    __syncthreads();

    float o[8];
    float s = 0.f, ss = 0.f;
    int   cch[2];
    #pragma unroll
    for (int k = 0; k < 2; ++k) {
        int f = tid + 512 * k;
        if (f < 896) {
            int c  = f / 14;
            int l0 = (f - c * 14) * 4;
            cch[k] = c;
            const float* row = sin_ + c * HW;
            #pragma unroll
            for (int q = 0; q < 4; ++q) {
                int l = l0 + q;
                float acc = bf[c];
                for (int j = 0; j < ksz; ++j) {
                    int idx = l + j - pad;
                    if (idx >= 0 && idx < HW) acc = fmaf(wf[c * ksz + j], row[idx], acc);
                }
                o[k * 4 + q] = acc;
                s += acc; ss = fmaf(acc, acc, ss);
            }
        } else cch[k] = -1;
    }
    int lane = tid & 31, wid = tid >> 5;
    #pragma unroll
    for (int off = 16; off; off >>= 1) { s += __shfl_xor_sync(~0u, s, off); ss += __shfl_xor_sync(~0u, ss, off); }
    if (lane == 0) { r1[wid] = s; r2[wid] = ss; }
    __syncthreads();
    if (tid == 0) {
        float a = 0.f, bs2 = 0.f;
        #pragma unroll
        for (int w = 0; w < 16; ++w) { a += r1[w]; bs2 += r2[w]; }
        float mean = a * (1.f / 3584.f);
        float var  = bs2 * (1.f / 3584.f) - mean * mean;
        sstat[0] = mean;
        sstat[1] = rsqrtf(var + EPS);
    }
    __syncthreads();
    float mean = sstat[0], rstd = sstat[1];
    #pragma unroll
    for (int k = 0; k < 2; ++k) {
        if (cch[k] >= 0) {
            int f = tid + 512 * k;
            int cg = g * 64 + cch[k];
            float a_ = rstd * sc[cg], b_ = bi[cg] - mean * a_;
            float4 v;
            v.x = 1.f / (1.f + __expf(-(o[k*4+0] * a_ + b_)));
            v.y = 1.f / (1.f + __expf(-(o[k*4+1] * a_ + b_)));
            v.z = 1.f / (1.f + __expf(-(o[k*4+2] * a_ + b_)));
            v.w = 1.f / (1.f + __expf(-(o[k*4+3] * a_ + b_)));
            out4[f] = v;
        }
    }
}

// ---------------- kernel 3: pooled xg + per-batch stats (register bands) ---
// 2 planes/block. Per plane: 112 threads, thread (band i, c4) sums its 7 rows
// in registers (ah per row, aw once), stores ONE float4 partial. No full-plane
// smem staging -> ~5x less L1 shared traffic.
__global__ __launch_bounds__(256) void k_pool(const float* __restrict__ x) {
    __shared__ __align__(16) float vs[2][8 * 60];   // [plane][band*60 + col]
    __shared__ __align__(16) float sah[2][HW];
    __shared__ __align__(16) float saw[2][HW];
    __shared__ float rs_[4], rss_[4];
    int pair = blockIdx.x, tid = threadIdx.x;
    int grp = tid >> 7;            // plane within pair (warps 0-3 / 4-7)
    int t   = tid & 127;
    int bc  = pair * 2 + grp;
    int b   = bc >> 8;             // both planes of pair share batch
    if (t < HW) {
        sah[grp][t] = g_attn_h[bc * HW + t];
        saw[grp][t] = g_attn_w[bc * HW + t];
    }
    __syncthreads();
    const float4* xp = (const float4*)(x + (size_t)bc * HW * HW);
    if (t < 112) {
        int i = t / 14, c4 = t - i * 14;
        float4 v[7];
        #pragma unroll
        for (int u = 0; u < 7; ++u) v[u] = xp[(7 * i + u) * 14 + c4];  // front-batched
        float4 acc = make_float4(0.f, 0.f, 0.f, 0.f);
        #pragma unroll
        for (int u = 0; u < 7; ++u) {
            float a = sah[grp][7 * i + u];
            acc.x = fmaf(v[u].x, a, acc.x);
            acc.y = fmaf(v[u].y, a, acc.y);
            acc.z = fmaf(v[u].z, a, acc.z);
            acc.w = fmaf(v[u].w, a, acc.w);
        }
        float4 w4 = ((const float4*)saw[grp])[c4];
        acc.x *= w4.x; acc.y *= w4.y; acc.z *= w4.z; acc.w *= w4.w;
        ((float4*)(vs[grp] + i * 60))[c4] = acc;
    }
    __syncthreads();
    float pv = 0.f;
    if (t < NN) {
        int i = t >> 3, j = t & 7;
        const float* p = vs[grp] + i * 60 + 7 * j;
        float sum = ((p[0] + p[1]) + (p[2] + p[3])) + ((p[4] + p[5]) + p[6]);
        pv = sum * (1.f / 49.f);
        g_pooled[bc * NN + t] = pv;
    }
    // stats: warps 0,1 (plane0) and 4,5 (plane1) carry nonzero pv
    float s = pv, ss = pv * pv;
    #pragma unroll
    for (int o = 16; o; o >>= 1) { s += __shfl_xor_sync(~0u, s, o); ss += __shfl_xor_sync(~0u, ss, o); }
    int lane = tid & 31, wid = tid >> 5;
    if (lane == 0 && (wid == 0 || wid == 1)) { rs_[wid] = s; rss_[wid] = ss; }
    if (lane == 0 && (wid == 4 || wid == 5)) { rs_[wid - 2] = s; rss_[wid - 2] = ss; }
    __syncthreads();
    if (tid == 0) {
        atomicAdd(&g_bsum[b],   (rs_[0]  + rs_[1])  + (rs_[2]  + rs_[3]));
        atomicAdd(&g_bsumsq[b], (rss_[0] + rss_[1]) + (rss_[2] + rss_[3]));
    }
}

// ---------------- kernel 4: attention -> channel gate ----------------------
__global__ __launch_bounds__(256) void k_attn(
    const float* __restrict__ ns, const float* __restrict__ nb,
    const float* __restrict__ qw, const float* __restrict__ kw,
    const float* __restrict__ vw)
{
    __shared__ __align__(16) float xs[HD * 68];
    __shared__ float svbar[HD];
    int h = blockIdx.x, b = blockIdx.y;
    float bs = g_bsum[b], bss = g_bsumsq[b];
    float mu = bs * (1.f / 16384.f);
    float var = bss * (1.f / 16384.f) - mu * mu;
    float rstd = rsqrtf(var + EPS);
    const float4* p4 = (const float4*)(g_pooled + ((size_t)b * C + h * HD) * NN);
    int tid = threadIdx.x;
    #pragma unroll
    for (int k = 0; k < 2; ++k) {
        int f = tid + 256 * k;
        float4 v = p4[f];
        int e = f >> 4;
        int c = h * HD + e;
        float a_ = rstd * ns[c], b_ = nb[c] - mu * a_;
        v.x = v.x * a_ + b_;
        v.y = v.y * a_ + b_;
        v.z = v.z * a_ + b_;
        v.w = v.w * a_ + b_;
        ((float4*)xs)[e * 17 + (f & 15)] = v;
    }
    __syncthreads();

    int wi = tid >> 5, lane = tid & 31;
    {
        float sv[4];
        #pragma unroll
        for (int dd = 0; dd < 4; ++dd) {
            int row = wi * 4 + dd;
            sv[dd] = xs[row * 68 + lane] + xs[row * 68 + lane + 32];
        }
        #pragma unroll
        for (int o = 16; o; o >>= 1)
            #pragma unroll
            for (int dd = 0; dd < 4; ++dd)
                sv[dd] += __shfl_xor_sync(~0u, sv[dd], o);
        if (lane == 0) {
            #pragma unroll
            for (int dd = 0; dd < 4; ++dd) {
                int row = wi * 4 + dd;
                svbar[row] = sv[dd] * (1.f / 64.f) * vw[h * HD + row];
            }
        }
    }
    __syncthreads();

    float kwe = kw[h * HD + lane];
    float vb  = svbar[lane];
    const float scale = 0.17677669529663687f;  // 32^-0.5
    int d0 = wi * 4;
    const float4* xs4 = (const float4*)xs;

    float acc[4];
    #pragma unroll
    for (int dd = 0; dd < 4; ++dd) acc[dd] = 0.f;
    #pragma unroll
    for (int j = 0; j < 16; ++j) {
        float4 t = xs4[lane * 17 + j];
        #pragma unroll
        for (int dd = 0; dd < 4; ++dd) {
            float4 q = xs4[(d0 + dd) * 17 + j];
            acc[dd] = fmaf(t.x, q.x, acc[dd]);
            acc[dd] = fmaf(t.y, q.y, acc[dd]);
            acc[dd] = fmaf(t.z, q.z, acc[dd]);
            acc[dd] = fmaf(t.w, q.w, acc[dd]);
        }
    }
    float sarr[4];
    #pragma unroll
    for (int dd = 0; dd < 4; ++dd)
        sarr[dd] = acc[dd] * qw[h * HD + d0 + dd] * kwe * scale;

    float m[4], pe[4], Z[4], num[4];
    #pragma unroll
    for (int dd = 0; dd < 4; ++dd) m[dd] = sarr[dd];
    #pragma unroll
    for (int o = 16; o; o >>= 1)
        #pragma unroll
        for (int dd = 0; dd < 4; ++dd)
            m[dd] = fmaxf(m[dd], __shfl_xor_sync(~0u, m[dd], o));
    #pragma unroll
    for (int dd = 0; dd < 4; ++dd) {
        pe[dd]  = __expf(sarr[dd] - m[dd]);
        Z[dd]   = pe[dd];
        num[dd] = pe[dd] * vb;
    }
    #pragma unroll
    for (int o = 16; o; o >>= 1)
        #pragma unroll
        for (int dd = 0; dd < 4; ++dd) {
            Z[dd]   += __shfl_xor_sync(~0u, Z[dd], o);
            num[dd] += __shfl_xor_sync(~0u, num[dd], o);
        }
    if (lane == 0) {
        #pragma unroll
        for (int dd = 0; dd < 4; ++dd)
            g_ca[b * C + h * HD + d0 + dd] = 1.f / (1.f + __expf(-(num[dd] / Z[dd])));
    }
}

// ---------------- kernel 5: out = ca * x * ah * aw -------------------------
__global__ __launch_bounds__(256) void k_final(const float* __restrict__ x,
                                               float* __restrict__ out) {
    __shared__ float sca[HW], saw[HW];
    int bc = blockIdx.x, tid = threadIdx.x;
    float ca = g_ca[bc];
    if (tid < HW)                     sca[tid] = ca * g_attn_h[bc * HW + tid];
    else if (tid >= 64 && tid < 120)  saw[tid - 64] = g_attn_w[bc * HW + tid - 64];
    __syncthreads();
    const float4* xp = (const float4*)(x + (size_t)bc * HW * HW);
    float4*       op = (float4*)(out + (size_t)bc * HW * HW);
    float4 v[4]; int f[4]; bool valid[4];
    #pragma unroll
    for (int k = 0; k < 4; ++k) {
        f[k] = tid + 256 * k;
        valid[k] = (f[k] < 784);
        if (valid[k]) v[k] = xp[f[k]];
    }
    #pragma unroll
    for (int k = 0; k < 4; ++k) {
        if (valid[k]) {
            int hrow = f[k] / 14;
            int w4   = (f[k] - hrow * 14) * 4;
            float s = sca[hrow];
            float4 o = v[k];
            o.x *= s * saw[w4 + 0];
            o.y *= s * saw[w4 + 1];
            o.z *= s * saw[w4 + 2];
            o.w *= s * saw[w4 + 3];
            op[f[k]] = o;
        }
    }
}

// ---------------- launch ---------------------------------------------------
extern "C" void kernel_launch(void* const* d_in, const int* in_sizes, int n_in,
                              void* d_out, int out_size) {
    const float* x  = (const float*)d_in[0];
    const float* w3 = (const float*)d_in[1];
    const float* b3 = (const float*)d_in[2];
    const float* w5 = (const float*)d_in[3];
    const float* b5 = (const float*)d_in[4];
    const float* w7 = (const float*)d_in[5];
    const float* b7 = (const float*)d_in[6];
    const float* w9 = (const float*)d_in[7];
    const float* b9 = (const float*)d_in[8];
    const float* nhs = (const float*)d_in[9];
    const float* nhb = (const float*)d_in[10];
    const float* nws = (const float*)d_in[11];
    const float* nwb = (const float*)d_in[12];
    const float* ns  = (const float*)d_in[13];
    const float* nb  = (const float*)d_in[14];
    const float* qw  = (const float*)d_in[15];
    const float* kw  = (const float*)d_in[16];
    const float* vw  = (const float*)d_in[17];
    float* out = (float*)d_out;

    k_tag<<<1, 32>>>();   // keeps ncu's fixed capture slot on k_pool
    k_means<<<BC, 256>>>(x);
    k_sa<<<dim3(4, B, 2), 512>>>(w3, b3, w5, b5, w7, b7, w9, b9, nhs, nhb, nws, nwb);
    k_pool<<<BC / 2, 256>>>(x);
    k_attn<<<dim3(HEADS, B), 256>>>(ns, nb, qw, kw, vw);
    k_final<<<BC, 256>>>(x, out);
}